// round 6
// baseline (speedup 1.0000x reference)
#include <cuda_runtime.h>

// Problem constants (fixed by setup_inputs: b=8, N=16384, d=128, T=64)
#define BDIM    8
#define NPIX    16384
#define DDIM    128
#define TDIM    64
#define NCAT    21
#define THRESHV 230.0f
#define XSTR    132     // x tile row stride: 33 granules, 33 % 32 == 1 -> conflict-free
#define PSTR    33      // partials row stride (odd -> conflict-free scalar reads)

// Output packing: flattened outputs concatenated in return order, float32.
#define OFF_MASK 2752512u                      // 8*16384*21
#define OFF_NCM  (OFF_MASK + 131072u)
#define OFF_MIND (OFF_NCM  + 131072u)
#define OFF_NC   (OFF_MIND + 131072u)

#define FMA2(acc, x, t) asm("fma.rn.f32x2 %0, %1, %2, %0;" : "+l"(acc) : "l"(x), "l"(t))

static __device__ __forceinline__ void upk2(unsigned long long v, float& a, float& b) {
    asm("mov.b64 {%0,%1}, %2;" : "=f"(a), "=f"(b) : "l"(v));
}

__global__ __launch_bounds__(256, 5) void nnos_kernel(
    const float* __restrict__ frame,   // [8, 16384, 128] f32
    const float* __restrict__ tmpl,    // [64, 16384, 128] f32
    const int*   __restrict__ tclass,  // [64] int32
    float*       __restrict__ out)
{
    __shared__ __align__(16) float x_s[BDIM * XSTR];   // 4224 B
    __shared__ float part[TDIM * PSTR];                // 8448 B
    __shared__ float x2_s[BDIM];

    const int n    = blockIdx.x;
    const int tid  = threadIdx.x;
    const int w    = tid >> 5;
    const int lane = tid & 31;

    // ---- Phase 1: frame row w -> smem + x2 reduction ----
    {
        float4 v = *(const float4*)(frame + (size_t)w * (NPIX * DDIM)
                                          + (size_t)n * DDIM + 4 * lane);
        *(float4*)(x_s + w * XSTR + 4 * lane) = v;
        float sq = v.x * v.x + v.y * v.y + v.z * v.z + v.w * v.w;
        #pragma unroll
        for (int off = 16; off; off >>= 1)
            sq += __shfl_xor_sync(0xffffffffu, sq, off);
        if (lane == 0) x2_s[w] = sq;
    }
    __syncthreads();

    // ---- Phase 2: warp w -> (t-half tg = w&1 of 32 templates, k-quarter kq = w>>1).
    //      lane -> templates {32tg + tt, 32tg + tt + 16}, batches 4*bh .. 4*bh+3.
    //      Templates read DIRECTLY from gmem: each warp owns an exclusive,
    //      contiguous 128B chunk per template row (perfectly coalesced).
    {
        const int tg = w & 1;
        const int kq = w >> 1;
        const int tt = lane & 15;
        const int bh = lane >> 4;
        const int t0 = tg * 32 + tt;
        const int t1 = t0 + 16;

        const size_t koff = (size_t)n * DDIM + kq * 32;
        const ulonglong2* __restrict__ tp0 =
            (const ulonglong2*)(tmpl + (size_t)t0 * (NPIX * DDIM) + koff);
        const ulonglong2* __restrict__ tp1 =
            (const ulonglong2*)(tmpl + (size_t)t1 * (NPIX * DDIM) + koff);
        const float* xr = x_s + (4 * bh) * XSTR + kq * 32;

        unsigned long long a0[4] = {0, 0, 0, 0};
        unsigned long long a1[4] = {0, 0, 0, 0};
        unsigned long long t2a0 = 0, t2a1 = 0;

        ulonglong2 c0 = tp0[0];
        ulonglong2 c1 = tp1[0];

        #pragma unroll
        for (int g = 0; g < 8; ++g) {
            const ulonglong2 tv0 = c0;
            const ulonglong2 tv1 = c1;
            if (g < 7) { c0 = tp0[g + 1]; c1 = tp1[g + 1]; }   // prefetch next 16B

            FMA2(t2a0, tv0.x, tv0.x); FMA2(t2a0, tv0.y, tv0.y);
            FMA2(t2a1, tv1.x, tv1.x); FMA2(t2a1, tv1.y, tv1.y);
            #pragma unroll
            for (int j = 0; j < 4; ++j) {
                ulonglong2 xv = *(const ulonglong2*)(xr + j * XSTR + g * 4);
                FMA2(a0[j], xv.x, tv0.x); FMA2(a0[j], xv.y, tv0.y);
                FMA2(a1[j], xv.x, tv1.x); FMA2(a1[j], xv.y, tv1.y);
            }
        }

        // Fold t2 into partials: part[t][8*kq + 4*bh + j] = t2q - 2*xtq
        float lo, hi;
        upk2(t2a0, lo, hi); const float t20 = lo + hi;
        upk2(t2a1, lo, hi); const float t21 = lo + hi;
        float* pr = part + (8 * kq + 4 * bh);
        #pragma unroll
        for (int j = 0; j < 4; ++j) {
            upk2(a0[j], lo, hi); pr[t0 * PSTR + j] = fmaf(-2.0f, lo + hi, t20);
            upk2(a1[j], lo, hi); pr[t1 * PSTR + j] = fmaf(-2.0f, lo + hi, t21);
        }
    }
    __syncthreads();

    // ---- Phase 3: warp w owns batch b = w; lanes scan t = lane, lane+32;
    //      butterfly argmin; fused epilogue ----
    {
        const int b = w;
        const float* p0 = part + lane * PSTR + b;
        const float* p1 = part + (lane + 32) * PSTR + b;

        float d  = (p0[0] + p0[8]) + (p0[16] + p0[24]);
        float d1 = (p1[0] + p1[8]) + (p1[16] + p1[24]);
        int  idx = lane;
        if (d1 < d) { d = d1; idx = lane + 32; }          // tie -> lower idx kept

        #pragma unroll
        for (int off = 16; off; off >>= 1) {
            float od = __shfl_xor_sync(0xffffffffu, d, off);
            int   oi = __shfl_xor_sync(0xffffffffu, idx, off);
            if (od < d || (od == d && oi < idx)) { d = od; idx = oi; }
        }
        const int   cls = tclass[idx];
        const float fd  = x2_s[b] + d;
        const int   msk = (fd <= THRESHV) ? 1 : 0;
        const size_t bn = (size_t)b * NPIX + n;

        if (lane == 0) {
            out[OFF_MASK + bn] = (float)msk;
            out[OFF_NCM  + bn] = (float)(msk ? cls : (NCAT - 1));
            out[OFF_MIND + bn] = fd;
            out[OFF_NC   + bn] = (float)cls;
        }
        if (lane < NCAT)
            out[bn * NCAT + lane] = (msk && (lane == cls)) ? 1.0f : 0.0f;
    }
}

extern "C" void kernel_launch(void* const* d_in, const int* in_sizes, int n_in,
                              void* d_out, int out_size) {
    const float* frame = (const float*)d_in[0];
    const float* tmpl  = (const float*)d_in[1];
    const int*   cls   = (const int*)d_in[2];
    float*       out   = (float*)d_out;
    (void)in_sizes; (void)n_in; (void)out_size;
    nnos_kernel<<<NPIX, 256>>>(frame, tmpl, cls, out);
}

// round 7
// speedup vs baseline: 3.3271x; 3.3271x over previous
#include <cuda_runtime.h>

// Problem constants (fixed by setup_inputs: b=8, N=16384, d=128, T=64)
#define BDIM    8
#define NPIX    16384
#define DDIM    128
#define TDIM    64
#define NCAT    21
#define THRESHV 230.0f
#define TSTRIDE 132     // t tile row stride: 33 granules, odd granule count -> good banks
#define XSTR    132     // x tile row stride
#define PSTR    33      // partials row stride (odd -> conflict-free scalar reads)

// Output packing: flattened outputs concatenated in return order, float32.
#define OFF_MASK 2752512u                      // 8*16384*21
#define OFF_NCM  (OFF_MASK + 131072u)
#define OFF_MIND (OFF_NCM  + 131072u)
#define OFF_NC   (OFF_MIND + 131072u)

#define FMA2(acc, x, t) asm("fma.rn.f32x2 %0, %1, %2, %0;" : "+l"(acc) : "l"(x), "l"(t))

static __device__ __forceinline__ void upk2(unsigned long long v, float& a, float& b) {
    asm("mov.b64 {%0,%1}, %2;" : "=f"(a), "=f"(b) : "l"(v));
}
static __device__ __forceinline__ void cpasync16(void* smem_dst, const void* gsrc) {
    unsigned d = (unsigned)__cvta_generic_to_shared(smem_dst);
    asm volatile("cp.async.cg.shared.global [%0], [%1], 16;\n" :: "r"(d), "l"(gsrc));
}

__global__ __launch_bounds__(256, 5) void nnos_kernel(
    const float* __restrict__ frame,   // [8, 16384, 128] f32
    const float* __restrict__ tmpl,    // [64, 16384, 128] f32
    const int*   __restrict__ tclass,  // [64] int32
    float*       __restrict__ out)
{
    // part[] aliases the head of t_s[] — t_s is dead once phase 2's reads finish.
    __shared__ __align__(16) float pool[TDIM * TSTRIDE];   // 33792 B  (t_s / part)
    __shared__ __align__(16) float x_s[BDIM * XSTR];       //  4224 B
    __shared__ float x2_s[BDIM];

    float* const t_s  = pool;
    float* const part = pool;            // 64*33 floats = 8448 B <= t_s size

    const int n    = blockIdx.x;
    const int tid  = threadIdx.x;
    const int w    = tid >> 5;
    const int lane = tid & 31;

    // ---- Phase 1a: stage templates via cp.async ----
    const size_t pixbase = (size_t)n * DDIM + 4 * lane;
    #pragma unroll
    for (int i = 0; i < 8; ++i) {
        const int r = i * 8 + w;
        cpasync16(t_s + r * TSTRIDE + 4 * lane,
                  tmpl + (size_t)r * (NPIX * DDIM) + pixbase);
    }
    asm volatile("cp.async.commit_group;\n");

    // ---- Phase 1b: frame row w -> smem + x2 reduction (overlaps async copies) ----
    {
        float4 v = *(const float4*)(frame + (size_t)w * (NPIX * DDIM) + pixbase);
        *(float4*)(x_s + w * XSTR + 4 * lane) = v;
        float sq = v.x * v.x + v.y * v.y + v.z * v.z + v.w * v.w;
        #pragma unroll
        for (int off = 16; off; off >>= 1)
            sq += __shfl_xor_sync(0xffffffffu, sq, off);
        if (lane == 0) x2_s[w] = sq;
    }
    asm volatile("cp.async.wait_group 0;\n");
    __syncthreads();

    // ---- Phase 2: warp w -> (t-half tg = w&1 of 32 templates, k-quarter kq = w>>1).
    //      lane -> templates {32tg + tt, 32tg + tt + 16}, batches 4*bh .. 4*bh+3.
    float res[BDIM];   // 8 partial distances (t0 x4, t1 x4), written after re-sync
    int   pt0, pkq, pbh;
    {
        const int tg = w & 1;
        const int kq = w >> 1;
        const int tt = lane & 15;
        const int bh = lane >> 4;
        const int t0 = tg * 32 + tt;
        const int t1 = t0 + 16;
        const int ko = kq * 32;
        pt0 = t0; pkq = kq; pbh = bh;

        const float* tr0 = t_s + t0 * TSTRIDE + ko;
        const float* tr1 = t_s + t1 * TSTRIDE + ko;
        const float* xr  = x_s + (4 * bh) * XSTR + ko;

        unsigned long long a0[4] = {0, 0, 0, 0};
        unsigned long long a1[4] = {0, 0, 0, 0};
        unsigned long long t2a0 = 0, t2a1 = 0;

        #pragma unroll
        for (int g = 0; g < 8; ++g) {
            ulonglong2 tv0 = *(const ulonglong2*)(tr0 + g * 4);
            ulonglong2 tv1 = *(const ulonglong2*)(tr1 + g * 4);
            FMA2(t2a0, tv0.x, tv0.x); FMA2(t2a0, tv0.y, tv0.y);
            FMA2(t2a1, tv1.x, tv1.x); FMA2(t2a1, tv1.y, tv1.y);
            #pragma unroll
            for (int j = 0; j < 4; ++j) {
                ulonglong2 xv = *(const ulonglong2*)(xr + j * XSTR + g * 4);
                FMA2(a0[j], xv.x, tv0.x); FMA2(a0[j], xv.y, tv0.y);
                FMA2(a1[j], xv.x, tv1.x); FMA2(a1[j], xv.y, tv1.y);
            }
        }

        // Collapse to partial distances: res = t2q - 2*xtq (x2 added in phase 3)
        float lo, hi;
        upk2(t2a0, lo, hi); const float t20 = lo + hi;
        upk2(t2a1, lo, hi); const float t21 = lo + hi;
        #pragma unroll
        for (int j = 0; j < 4; ++j) {
            upk2(a0[j], lo, hi); res[j]     = fmaf(-2.0f, lo + hi, t20);
            upk2(a1[j], lo, hi); res[4 + j] = fmaf(-2.0f, lo + hi, t21);
        }
    }
    __syncthreads();   // all t_s reads complete -> safe to overwrite with part[]

    {
        float* pr = part + (8 * pkq + 4 * pbh);
        #pragma unroll
        for (int j = 0; j < 4; ++j) {
            pr[pt0 * PSTR + j]        = res[j];
            pr[(pt0 + 16) * PSTR + j] = res[4 + j];
        }
    }
    __syncthreads();

    // ---- Phase 3: warp w owns batch b = w; lanes scan t = lane, lane+32;
    //      butterfly argmin; fused epilogue ----
    {
        const int b = w;
        const float* p0 = part + lane * PSTR + b;
        const float* p1 = part + (lane + 32) * PSTR + b;

        float d  = (p0[0] + p0[8]) + (p0[16] + p0[24]);
        float d1 = (p1[0] + p1[8]) + (p1[16] + p1[24]);
        int  idx = lane;
        if (d1 < d) { d = d1; idx = lane + 32; }          // tie -> lower idx kept

        #pragma unroll
        for (int off = 16; off; off >>= 1) {
            float od = __shfl_xor_sync(0xffffffffu, d, off);
            int   oi = __shfl_xor_sync(0xffffffffu, idx, off);
            if (od < d || (od == d && oi < idx)) { d = od; idx = oi; }
        }
        const int   cls = tclass[idx];
        const float fd  = x2_s[b] + d;
        const int   msk = (fd <= THRESHV) ? 1 : 0;
        const size_t bn = (size_t)b * NPIX + n;

        if (lane == 0) {
            out[OFF_MASK + bn] = (float)msk;
            out[OFF_NCM  + bn] = (float)(msk ? cls : (NCAT - 1));
            out[OFF_MIND + bn] = fd;
            out[OFF_NC   + bn] = (float)cls;
        }
        if (lane < NCAT)
            out[bn * NCAT + lane] = (msk && (lane == cls)) ? 1.0f : 0.0f;
    }
}

extern "C" void kernel_launch(void* const* d_in, const int* in_sizes, int n_in,
                              void* d_out, int out_size) {
    const float* frame = (const float*)d_in[0];
    const float* tmpl  = (const float*)d_in[1];
    const int*   cls   = (const int*)d_in[2];
    float*       out   = (float*)d_out;
    (void)in_sizes; (void)n_in; (void)out_size;
    nnos_kernel<<<NPIX, 256>>>(frame, tmpl, cls, out);
}